// round 11
// baseline (speedup 1.0000x reference)
#include <cuda_runtime.h>
#include <cuda_fp16.h>
#include <math_constants.h>
#include <cstdint>

#define NN_NODES 20000
#define EE_EDGES 320000
#define FF 128
#define HH1 3

// ---------------- scratch (static device allocations) ----------------
__device__ float g_h1[NN_NODES * HH1 * FF];
__device__ float g_h2[NN_NODES * FF];
__device__ float g_el1[NN_NODES * 4];
__device__ float g_er1[NN_NODES * 4];
__device__ float g_el2[NN_NODES];
__device__ float g_er2[NN_NODES];
__device__ int   g_row[NN_NODES + 1];
__device__ int   g_cursor[NN_NODES];
__device__ int   g_srcp[EE_EDGES];
__device__ int   g_bsums[64];
// A operands [M, 2K] = exact fp16 (hi | lo); B operands [NCOLS, K] = fp16(W^T)
__device__ __align__(16) __half g_a1cat[NN_NODES * 256];
__device__ __align__(16) __half g_a2cat[(size_t)NN_NODES * 768];
__device__ __align__(16) __half g_b1cat[384 * 128];
__device__ __align__(16) __half g_b2cat[128 * 384];

// ---------------- helpers ----------------
__device__ __forceinline__ uint32_t smem_u32(const void* p) {
    uint32_t a;
    asm("{ .reg .u64 t; cvta.to.shared.u64 t, %1; cvt.u32.u64 %0, t; }" : "=r"(a) : "l"(p));
    return a;
}
#define LDSM_X4(r0, r1, r2, r3, addr) \
    asm volatile("ldmatrix.sync.aligned.m8n8.x4.shared.b16 {%0,%1,%2,%3}, [%4];" \
                 : "=r"(r0), "=r"(r1), "=r"(r2), "=r"(r3) : "r"(addr))

__device__ __forceinline__ void mma16816(float* d, const uint32_t* a, const uint32_t* b) {
    asm volatile(
        "mma.sync.aligned.m16n8k16.row.col.f32.f16.f16.f32 "
        "{%0,%1,%2,%3}, {%4,%5,%6,%7}, {%8,%9}, {%0,%1,%2,%3};"
        : "+f"(d[0]), "+f"(d[1]), "+f"(d[2]), "+f"(d[3])
        : "r"(a[0]), "r"(a[1]), "r"(a[2]), "r"(a[3]), "r"(b[0]), "r"(b[1]));
}
__device__ __forceinline__ void cp16(uint32_t saddr, const void* g, uint32_t sz) {
    asm volatile("cp.async.cg.shared.global [%0], [%1], 16, %2;"
                 :: "r"(saddr), "l"(g), "r"(sz) : "memory");
}
#define CP_COMMIT() asm volatile("cp.async.commit_group;" ::: "memory")
#define CP_WAIT1()  asm volatile("cp.async.wait_group 1;" ::: "memory")

// ---------------- fp16 mma.sync GEMM, MROWS=64 tile, 3 CTAs/SM, 3-stage cp.async ----------------
// C[M,NCOLS] = A[M,2K] @ B'[NCOLS,2K]^T where B'[., k'] = B[., k' mod K] (B stored [NCOLS,K]).
// A = (hi|lo) exact fp16 split => C = A_fp32 @ fp16(B)^T with fp32 accumulate.
// blockIdx.y = 128-col chunk = head; emits fused el/er.
template <int MROWS>
__global__ __launch_bounds__(256, 3) void gemm_mma(const __half* __restrict__ A,
                                                   const __half* __restrict__ B,
                                                   float* __restrict__ C,
                                                   int M, int K, int NCOLS,
                                                   const float* __restrict__ al,
                                                   const float* __restrict__ ar,
                                                   float* __restrict__ el,
                                                   float* __restrict__ er, int st) {
    extern __shared__ __align__(16) uint8_t smem[];  // 3 stages of [A MROWS*128 | B 16384]
    constexpr int ASTAGE = MROWS * 128;
    constexpr int STAGE = ASTAGE + 16384;
    constexpr int MT = MROWS / 32;
    constexpr int AP = MROWS / 32;
    const int tid = threadIdx.x, lane = tid & 31, wid = tid >> 5;
    const int bm = blockIdx.x, bn = blockIdx.y;
    const int wm = (wid & 1) * (MROWS / 2), wn = (wid >> 1) * 32;
    const uint32_t sbase = smem_u32(smem);
    const int Kp = 2 * K;

    float acc[MT][4][4];
    #pragma unroll
    for (int i = 0; i < MT; i++)
        #pragma unroll
        for (int j = 0; j < 4; j++)
            #pragma unroll
            for (int q = 0; q < 4; q++) acc[i][j][q] = 0.f;

    const int lrow = ((lane >> 3) & 1) * 8 + (lane & 7);
    const int lch = lane >> 4;

    uint32_t aro[MT], arx[MT], bro[2], brx[2];
    #pragma unroll
    for (int mt = 0; mt < MT; mt++) {
        int r = wm + mt * 16 + lrow;
        aro[mt] = (uint32_t)(r * 128);
        arx[mt] = (uint32_t)(r & 7);
    }
    #pragma unroll
    for (int h = 0; h < 2; h++) {
        int r = wn + h * 16 + lrow;
        bro[h] = (uint32_t)(r * 128);
        brx[h] = (uint32_t)(r & 7);
    }

    int alr[AP], alc[AP];
    uint32_t aso[AP];
    #pragma unroll
    for (int p = 0; p < AP; p++) {
        int g = tid + p * 256;
        alr[p] = g >> 3;
        alc[p] = g & 7;
        aso[p] = (uint32_t)(alr[p] * 128 + ((alc[p] ^ (alr[p] & 7)) << 4));
    }
    int blr[4], blc[4];
    uint32_t bso[4];
    #pragma unroll
    for (int p = 0; p < 4; p++) {
        int g = tid + p * 256;
        blr[p] = g >> 3;
        blc[p] = g & 7;
        bso[p] = (uint32_t)(blr[p] * 128 + ((blc[p] ^ (blr[p] & 7)) << 4));
    }

    auto issue = [&](int stage, int kn) {
        int bbase = (kn < K) ? kn : kn - K;
        uint32_t sa = sbase + stage * STAGE;
        uint32_t sb = sa + ASTAGE;
        #pragma unroll
        for (int p = 0; p < AP; p++) {
            int gr = bm * MROWS + alr[p];
            cp16(sa + aso[p], A + (size_t)gr * Kp + kn + alc[p] * 8,
                 (gr < M) ? 16u : 0u);
        }
        #pragma unroll
        for (int p = 0; p < 4; p++)
            cp16(sb + bso[p], B + (size_t)(bn * 128 + blr[p]) * K + bbase + blc[p] * 8, 16u);
        CP_COMMIT();
    };

    issue(0, 0);
    issue(1, 64);

    const int nchunks = Kp >> 6;
    for (int ck = 0; ck < nchunks; ck++) {
        CP_WAIT1();
        __syncthreads();
        if (ck + 2 < nchunks) issue((ck + 2) % 3, (ck + 2) * 64);
        else CP_COMMIT();
        uint32_t sAb = sbase + (ck % 3) * STAGE;
        uint32_t sBb = sAb + ASTAGE;
        #pragma unroll
        for (int ks = 0; ks < 4; ks++) {
            const uint32_t c = (uint32_t)(ks * 2 + lch);
            uint32_t af[MT][4];
            #pragma unroll
            for (int mt = 0; mt < MT; mt++)
                LDSM_X4(af[mt][0], af[mt][1], af[mt][2], af[mt][3],
                        sAb + aro[mt] + ((c ^ arx[mt]) << 4));
            uint32_t bf[4][2];
            #pragma unroll
            for (int h = 0; h < 2; h++) {
                uint32_t t0, t1, t2, t3;
                LDSM_X4(t0, t1, t2, t3, sBb + bro[h] + ((c ^ brx[h]) << 4));
                bf[h * 2 + 0][0] = t0; bf[h * 2 + 0][1] = t2;
                bf[h * 2 + 1][0] = t1; bf[h * 2 + 1][1] = t3;
            }
            #pragma unroll
            for (int mt = 0; mt < MT; mt++)
                #pragma unroll
                for (int nt = 0; nt < 4; nt++)
                    mma16816(acc[mt][nt], af[mt], bf[nt]);
        }
    }
    __syncthreads();

    // ---- C write + fused score partials ----
    float ps[MT][4];
    #pragma unroll
    for (int mt = 0; mt < MT; mt++) {
        int gr0 = bm * MROWS + wm + mt * 16 + (lane >> 2);
        float pl0 = 0.f, pr0 = 0.f, pl1 = 0.f, pr1 = 0.f;
        #pragma unroll
        for (int nt = 0; nt < 4; nt++) {
            int col = wn + nt * 8 + (lane & 3) * 2;
            int gc = bn * 128 + col;
            if (gr0 < M)
                *(float2*)(C + (size_t)gr0 * NCOLS + gc) =
                    make_float2(acc[mt][nt][0], acc[mt][nt][1]);
            if (gr0 + 8 < M)
                *(float2*)(C + (size_t)(gr0 + 8) * NCOLS + gc) =
                    make_float2(acc[mt][nt][2], acc[mt][nt][3]);
            float a0 = al[gc], a1 = al[gc + 1];
            float b0 = ar[gc], b1 = ar[gc + 1];
            pl0 += acc[mt][nt][0] * a0 + acc[mt][nt][1] * a1;
            pr0 += acc[mt][nt][0] * b0 + acc[mt][nt][1] * b1;
            pl1 += acc[mt][nt][2] * a0 + acc[mt][nt][3] * a1;
            pr1 += acc[mt][nt][2] * b0 + acc[mt][nt][3] * b1;
        }
        #pragma unroll
        for (int o = 1; o <= 2; o <<= 1) {
            pl0 += __shfl_xor_sync(0xffffffffu, pl0, o);
            pr0 += __shfl_xor_sync(0xffffffffu, pr0, o);
            pl1 += __shfl_xor_sync(0xffffffffu, pl1, o);
            pr1 += __shfl_xor_sync(0xffffffffu, pr1, o);
        }
        ps[mt][0] = pl0; ps[mt][1] = pr0; ps[mt][2] = pl1; ps[mt][3] = pr1;
    }
    __syncthreads();
    float (*s_sl)[4] = (float(*)[4])smem;
    float (*s_sr)[4] = (float(*)[4])(smem + MROWS * 16);
    int wn4 = wid >> 1;
    if ((lane & 3) == 0) {
        #pragma unroll
        for (int mt = 0; mt < MT; mt++) {
            int lr0 = wm + mt * 16 + (lane >> 2);
            s_sl[lr0][wn4] = ps[mt][0];
            s_sr[lr0][wn4] = ps[mt][1];
            s_sl[lr0 + 8][wn4] = ps[mt][2];
            s_sr[lr0 + 8][wn4] = ps[mt][3];
        }
    }
    __syncthreads();
    if (tid < MROWS) {
        int row = bm * MROWS + tid;
        if (row < M) {
            float sl = s_sl[tid][0] + s_sl[tid][1] + s_sl[tid][2] + s_sl[tid][3];
            float sr = s_sr[tid][0] + s_sr[tid][1] + s_sr[tid][2] + s_sr[tid][3];
            el[row * st + bn] = sl;
            er[row * st + bn] = sr;
        }
    }
}

// ---------------- merged prep: A1 exact fp16 split + fp16 weight transposes ----------------
__global__ void prep_all(const float* __restrict__ feats, const float* __restrict__ W1,
                         const float* __restrict__ W2, __half* __restrict__ a1,
                         __half* __restrict__ b1, __half* __restrict__ b2) {
    int i = blockIdx.x * blockDim.x + threadIdx.x;
    const int SA = NN_NODES * FF;
    const int S1 = 384 * 128;
    const int S2 = 128 * 384;
    if (i < SA) {
        int n = i >> 7, k = i & 127;
        float v = feats[i];
        __half h = __float2half_rn(v);
        __half l = __float2half_rn(v - __half2float(h));
        size_t base = (size_t)n * 256 + k;
        a1[base] = h;
        a1[base + 128] = l;
    } else if (i < SA + S1) {
        int j = i - SA;
        int n = j >> 7, k = j & 127;
        b1[j] = __float2half_rn(W1[k * 384 + n]);
    } else if (i < SA + S1 + S2) {
        int j = i - SA - S1;
        int n = j / 384, k = j % 384;
        b2[j] = __float2half_rn(W2[k * 128 + n]);
    }
}

// ---------------- CSR build ----------------
__global__ void zero_counts_k(int* row) {
    int i = blockIdx.x * blockDim.x + threadIdx.x;
    if (i <= NN_NODES) row[i] = 0;
}
__global__ void count_k(const int* __restrict__ dst, int* row) {
    int e = blockIdx.x * blockDim.x + threadIdx.x;
    if (e < EE_EDGES) atomicAdd(&row[dst[e]], 1);
}
__global__ void scan_block_k(int* __restrict__ row, int* __restrict__ bsums, int n) {
    __shared__ int sm[512];
    int i = blockIdx.x * 512 + threadIdx.x;
    int v = (i < n) ? row[i] : 0;
    sm[threadIdx.x] = v;
    __syncthreads();
    #pragma unroll
    for (int off = 1; off < 512; off <<= 1) {
        int t = (threadIdx.x >= off) ? sm[threadIdx.x - off] : 0;
        __syncthreads();
        sm[threadIdx.x] += t;
        __syncthreads();
    }
    int incl = sm[threadIdx.x];
    if (i < n) row[i] = incl - v;
    if (threadIdx.x == 511) bsums[blockIdx.x] = incl;
}
__global__ void scan_add_k(int* __restrict__ row, const int* __restrict__ bsums,
                           int* __restrict__ cursor, int n, int nb) {
    __shared__ int sb[65];
    int tid = threadIdx.x;
    if (tid == 0) sb[0] = 0;
    if (tid < 64) {
        int v = (tid < nb) ? bsums[tid] : 0;
        int lane = tid & 31;
        #pragma unroll
        for (int o = 1; o < 32; o <<= 1) {
            int t = __shfl_up_sync(0xffffffffu, v, o);
            if (lane >= o) v += t;
        }
        sb[tid + 1] = v;
    }
    __syncthreads();
    if (tid >= 32 && tid < 64) sb[tid + 1] += sb[32];
    __syncthreads();
    int i = blockIdx.x * blockDim.x + tid;
    if (i < n) {
        int v = row[i] + sb[i >> 9];
        row[i] = v;
        cursor[i] = v;
    }
    if (i == 0) row[n] = EE_EDGES;
}
__global__ void scatter_k(const int* __restrict__ src, const int* __restrict__ dst,
                          int* cursor, int* __restrict__ srcp) {
    int e = blockIdx.x * blockDim.x + threadIdx.x;
    if (e < EE_EDGES) {
        int p = atomicAdd(&cursor[dst[e]], 1);
        srcp[p] = src[e];
    }
}

// ---------------- aggregation, 4-way batched gathers: warp per (dst, head) ----------------
template <int HEADS, int ST, bool FP16OUT>
__global__ void agg_k(const float* __restrict__ hfeat, const float* __restrict__ el,
                      const float* __restrict__ er, const float* __restrict__ bias,
                      const int* __restrict__ row, const int* __restrict__ srcp,
                      float* __restrict__ out, __half* __restrict__ ocat) {
    int wg = (blockIdx.x * blockDim.x + threadIdx.x) >> 5;
    int lane = threadIdx.x & 31;
    if (wg >= NN_NODES * HEADS) return;
    int d = wg / HEADS, h = wg - d * HEADS;
    int s0 = row[d], s1 = row[d + 1];
    float erd = er[d * ST + h];

    float4 acc = make_float4(0.f, 0.f, 0.f, 0.f);
    float den = 0.f;
    int i = s0;
    for (; i + 4 <= s1; i += 4) {
        // batch all loads: 4 srcp, then 4 el gathers, then 4 feature gathers
        int s0i = srcp[i], s1i = srcp[i + 1], s2i = srcp[i + 2], s3i = srcp[i + 3];
        float e0 = el[s0i * ST + h], e1 = el[s1i * ST + h];
        float e2 = el[s2i * ST + h], e3 = el[s3i * ST + h];
        const float* f0 = hfeat + (size_t)s0i * (HEADS * 128) + h * 128 + lane * 4;
        const float* f1 = hfeat + (size_t)s1i * (HEADS * 128) + h * 128 + lane * 4;
        const float* f2 = hfeat + (size_t)s2i * (HEADS * 128) + h * 128 + lane * 4;
        const float* f3 = hfeat + (size_t)s3i * (HEADS * 128) + h * 128 + lane * 4;
        float4 v0 = *(const float4*)f0;
        float4 v1 = *(const float4*)f1;
        float4 v2 = *(const float4*)f2;
        float4 v3 = *(const float4*)f3;
        e0 += erd; e0 = (e0 > 0.f) ? e0 : 0.2f * e0;
        e1 += erd; e1 = (e1 > 0.f) ? e1 : 0.2f * e1;
        e2 += erd; e2 = (e2 > 0.f) ? e2 : 0.2f * e2;
        e3 += erd; e3 = (e3 > 0.f) ? e3 : 0.2f * e3;
        float w0 = __expf(e0), w1 = __expf(e1), w2 = __expf(e2), w3 = __expf(e3);
        den += (w0 + w1) + (w2 + w3);
        acc.x += w0 * v0.x + w1 * v1.x + w2 * v2.x + w3 * v3.x;
        acc.y += w0 * v0.y + w1 * v1.y + w2 * v2.y + w3 * v3.y;
        acc.z += w0 * v0.z + w1 * v1.z + w2 * v2.z + w3 * v3.z;
        acc.w += w0 * v0.w + w1 * v1.w + w2 * v2.w + w3 * v3.w;
    }
    for (; i < s1; ++i) {
        int s = srcp[i];
        float e = el[s * ST + h] + erd;
        e = (e > 0.f) ? e : 0.2f * e;
        float wt = __expf(e);
        den += wt;
        float4 v = *(const float4*)(hfeat + (size_t)s * (HEADS * 128) + h * 128 + lane * 4);
        acc.x += wt * v.x;
        acc.y += wt * v.y;
        acc.z += wt * v.z;
        acc.w += wt * v.w;
    }
    float inv = 1.0f / den;
    float4 b4 = *(const float4*)(bias + h * 128 + lane * 4);
    float r[4] = {acc.x * inv + b4.x, acc.y * inv + b4.y,
                  acc.z * inv + b4.z, acc.w * inv + b4.w};
    if (FP16OUT) {
        __half hv[4], lv[4];
        #pragma unroll
        for (int q = 0; q < 4; q++) {
            hv[q] = __float2half_rn(r[q]);
            lv[q] = __float2half_rn(r[q] - __half2float(hv[q]));
        }
        size_t base = (size_t)d * 768 + h * 128 + lane * 4;
        *(uint2*)(ocat + base) = *(uint2*)hv;
        *(uint2*)(ocat + base + 384) = *(uint2*)lv;
    } else {
        *(float4*)(out + (size_t)d * (HEADS * 128) + h * 128 + lane * 4) =
            make_float4(r[0], r[1], r[2], r[3]);
    }
}

// ---------------- launch ----------------
static inline int cdiv(int a, int b) { return (a + b - 1) / b; }

extern "C" void kernel_launch(void* const* d_in, const int* in_sizes, int n_in,
                              void* d_out, int out_size) {
    const float* feats   = (const float*)d_in[0];
    const float* W1      = (const float*)d_in[1];
    const float* attn_l1 = (const float*)d_in[2];
    const float* attn_r1 = (const float*)d_in[3];
    const float* bias1   = (const float*)d_in[4];
    const float* W2      = (const float*)d_in[5];
    const float* attn_l2 = (const float*)d_in[6];
    const float* attn_r2 = (const float*)d_in[7];
    const float* bias2   = (const float*)d_in[8];
    const int*   src     = (const int*)d_in[9];
    const int*   dst     = (const int*)d_in[10];
    float* out = (float*)d_out;

    float *h1, *h2, *el1, *er1, *el2, *er2;
    int *row, *cursor, *srcp, *bsums;
    __half *a1cat, *a2cat, *b1cat, *b2cat;
    cudaGetSymbolAddress((void**)&h1, g_h1);
    cudaGetSymbolAddress((void**)&h2, g_h2);
    cudaGetSymbolAddress((void**)&el1, g_el1);
    cudaGetSymbolAddress((void**)&er1, g_er1);
    cudaGetSymbolAddress((void**)&el2, g_el2);
    cudaGetSymbolAddress((void**)&er2, g_er2);
    cudaGetSymbolAddress((void**)&row, g_row);
    cudaGetSymbolAddress((void**)&cursor, g_cursor);
    cudaGetSymbolAddress((void**)&srcp, g_srcp);
    cudaGetSymbolAddress((void**)&bsums, g_bsums);
    cudaGetSymbolAddress((void**)&a1cat, g_a1cat);
    cudaGetSymbolAddress((void**)&a2cat, g_a2cat);
    cudaGetSymbolAddress((void**)&b1cat, g_b1cat);
    cudaGetSymbolAddress((void**)&b2cat, g_b2cat);

    static cudaStream_t s2 = nullptr;
    static cudaEvent_t evFork = nullptr, evJoin = nullptr;
    static bool attrDone = false;
    if (!s2) {
        cudaStreamCreateWithFlags(&s2, cudaStreamNonBlocking);
        cudaEventCreateWithFlags(&evFork, cudaEventDisableTiming);
        cudaEventCreateWithFlags(&evJoin, cudaEventDisableTiming);
    }
    if (!attrDone) {
        cudaFuncSetAttribute(gemm_mma<64>, cudaFuncAttributeMaxDynamicSharedMemorySize,
                             3 * (64 * 128 + 16384));
        attrDone = true;
    }

    const int nb = cdiv(NN_NODES, 512);
    const int smemSz = 3 * (64 * 128 + 16384);  // 73728

    // fork CSR head on side stream
    cudaEventRecord(evFork, 0);
    cudaStreamWaitEvent(s2, evFork, 0);
    zero_counts_k<<<cdiv(NN_NODES + 1, 256), 256, 0, s2>>>(row);             // 1
    count_k<<<cdiv(EE_EDGES, 256), 256, 0, s2>>>(dst, row);                  // 2
    prep_all<<<cdiv(NN_NODES * FF + 2 * 384 * 128, 256), 256>>>(             // 3
        feats, W1, W2, a1cat, b1cat, b2cat);
    {
        dim3 grid(cdiv(NN_NODES, 64), 3);
        gemm_mma<64><<<grid, 256, smemSz>>>(                                 // 4 (profiled)
            a1cat, b1cat, h1, NN_NODES, 128, 384, attn_l1, attn_r1, el1, er1, 4);
    }
    scan_block_k<<<nb, 512, 0, s2>>>(row, bsums, NN_NODES);                  // 5
    scan_add_k<<<cdiv(NN_NODES, 256), 256, 0, s2>>>(row, bsums, cursor, NN_NODES, nb); // 6
    scatter_k<<<cdiv(EE_EDGES, 256), 256, 0, s2>>>(src, dst, cursor, srcp);  // 7
    cudaEventRecord(evJoin, s2);

    cudaStreamWaitEvent(0, evJoin, 0);
    agg_k<HH1, 4, true><<<cdiv(NN_NODES * HH1 * 32, 256), 256>>>(            // 8
        h1, el1, er1, bias1, row, srcp, nullptr, a2cat);

    {
        dim3 grid(cdiv(NN_NODES, 64), 1);
        gemm_mma<64><<<grid, 256, smemSz>>>(                                 // 9
            a2cat, b2cat, h2, NN_NODES, 384, 128, attn_l2, attn_r2, el2, er2, 1);
    }
    agg_k<1, 1, false><<<cdiv(NN_NODES * 32, 256), 256>>>(                   // 10
        h2, el2, er2, bias2, row, srcp, out, nullptr);
}

// round 12
// speedup vs baseline: 1.2238x; 1.2238x over previous
#include <cuda_runtime.h>
#include <cuda_fp16.h>
#include <math_constants.h>
#include <cstdint>

#define NN_NODES 20000
#define EE_EDGES 320000
#define FF 128
#define HH1 3

// ---------------- scratch (static device allocations) ----------------
__device__ float g_h1[NN_NODES * HH1 * FF];
__device__ float g_h2[NN_NODES * FF];
__device__ float g_el1[NN_NODES * 4];
__device__ float g_er1[NN_NODES * 4];
__device__ float g_el2[NN_NODES];
__device__ float g_er2[NN_NODES];
__device__ int   g_row[NN_NODES + 1];
__device__ int   g_cursor[NN_NODES];
__device__ int   g_srcp[EE_EDGES];
__device__ int   g_bsums[64];
// fp16 operands: A [M,K], B [NCOLS,K] = fp16(W^T)
__device__ __align__(16) __half g_a1cat[NN_NODES * 128];
__device__ __align__(16) __half g_a2cat[(size_t)NN_NODES * 384];
__device__ __align__(16) __half g_b1cat[384 * 128];
__device__ __align__(16) __half g_b2cat[128 * 384];

// ---------------- helpers ----------------
__device__ __forceinline__ uint32_t smem_u32(const void* p) {
    uint32_t a;
    asm("{ .reg .u64 t; cvta.to.shared.u64 t, %1; cvt.u32.u64 %0, t; }" : "=r"(a) : "l"(p));
    return a;
}
#define LDSM_X4(r0, r1, r2, r3, addr) \
    asm volatile("ldmatrix.sync.aligned.m8n8.x4.shared.b16 {%0,%1,%2,%3}, [%4];" \
                 : "=r"(r0), "=r"(r1), "=r"(r2), "=r"(r3) : "r"(addr))

__device__ __forceinline__ void mma16816(float* d, const uint32_t* a, const uint32_t* b) {
    asm volatile(
        "mma.sync.aligned.m16n8k16.row.col.f32.f16.f16.f32 "
        "{%0,%1,%2,%3}, {%4,%5,%6,%7}, {%8,%9}, {%0,%1,%2,%3};"
        : "+f"(d[0]), "+f"(d[1]), "+f"(d[2]), "+f"(d[3])
        : "r"(a[0]), "r"(a[1]), "r"(a[2]), "r"(a[3]), "r"(b[0]), "r"(b[1]));
}
__device__ __forceinline__ void cp16(uint32_t saddr, const void* g, uint32_t sz) {
    asm volatile("cp.async.cg.shared.global [%0], [%1], 16, %2;"
                 :: "r"(saddr), "l"(g), "r"(sz) : "memory");
}
#define CP_COMMIT() asm volatile("cp.async.commit_group;" ::: "memory")
#define CP_WAIT1()  asm volatile("cp.async.wait_group 1;" ::: "memory")

// ---------------- fp16 mma.sync GEMM (single product), 3-stage cp.async ----------------
// C[M,NCOLS](fp32) = A[M,K](fp16) @ B[NCOLS,K](fp16)^T, fp32 accumulate.
// blockIdx.y = 128-col chunk = head; emits fused el/er from fp32 accumulators.
template <int MROWS>
__global__ __launch_bounds__(256) void gemm_mma(const __half* __restrict__ A,
                                                const __half* __restrict__ B,
                                                float* __restrict__ C,
                                                int M, int K, int NCOLS,
                                                const float* __restrict__ al,
                                                const float* __restrict__ ar,
                                                float* __restrict__ el,
                                                float* __restrict__ er, int st) {
    extern __shared__ __align__(16) uint8_t smem[];  // 3 stages of [A MROWS*128 | B 16384]
    constexpr int ASTAGE = MROWS * 128;
    constexpr int STAGE = ASTAGE + 16384;
    constexpr int MT = MROWS / 32;
    constexpr int AP = MROWS / 32;
    const int tid = threadIdx.x, lane = tid & 31, wid = tid >> 5;
    const int bm = blockIdx.x, bn = blockIdx.y;
    const int wm = (wid & 1) * (MROWS / 2), wn = (wid >> 1) * 32;
    const uint32_t sbase = smem_u32(smem);

    float acc[MT][4][4];
    #pragma unroll
    for (int i = 0; i < MT; i++)
        #pragma unroll
        for (int j = 0; j < 4; j++)
            #pragma unroll
            for (int q = 0; q < 4; q++) acc[i][j][q] = 0.f;

    const int lrow = ((lane >> 3) & 1) * 8 + (lane & 7);
    const int lch = lane >> 4;

    uint32_t aro[MT], arx[MT], bro[2], brx[2];
    #pragma unroll
    for (int mt = 0; mt < MT; mt++) {
        int r = wm + mt * 16 + lrow;
        aro[mt] = (uint32_t)(r * 128);
        arx[mt] = (uint32_t)(r & 7);
    }
    #pragma unroll
    for (int h = 0; h < 2; h++) {
        int r = wn + h * 16 + lrow;
        bro[h] = (uint32_t)(r * 128);
        brx[h] = (uint32_t)(r & 7);
    }

    int alr[AP], alc[AP];
    uint32_t aso[AP];
    #pragma unroll
    for (int p = 0; p < AP; p++) {
        int g = tid + p * 256;
        alr[p] = g >> 3;
        alc[p] = g & 7;
        aso[p] = (uint32_t)(alr[p] * 128 + ((alc[p] ^ (alr[p] & 7)) << 4));
    }
    int blr[4], blc[4];
    uint32_t bso[4];
    #pragma unroll
    for (int p = 0; p < 4; p++) {
        int g = tid + p * 256;
        blr[p] = g >> 3;
        blc[p] = g & 7;
        bso[p] = (uint32_t)(blr[p] * 128 + ((blc[p] ^ (blr[p] & 7)) << 4));
    }

    auto issue = [&](int stage, int kn) {
        uint32_t sa = sbase + stage * STAGE;
        uint32_t sb = sa + ASTAGE;
        #pragma unroll
        for (int p = 0; p < AP; p++) {
            int gr = bm * MROWS + alr[p];
            cp16(sa + aso[p], A + (size_t)gr * K + kn + alc[p] * 8,
                 (gr < M) ? 16u : 0u);
        }
        #pragma unroll
        for (int p = 0; p < 4; p++)
            cp16(sb + bso[p], B + (size_t)(bn * 128 + blr[p]) * K + kn + blc[p] * 8, 16u);
        CP_COMMIT();
    };

    issue(0, 0);
    if (K > 64) issue(1, 64);
    else CP_COMMIT();

    const int nchunks = K >> 6;
    for (int ck = 0; ck < nchunks; ck++) {
        CP_WAIT1();
        __syncthreads();
        if (ck + 2 < nchunks) issue((ck + 2) % 3, (ck + 2) * 64);
        else CP_COMMIT();
        uint32_t sAb = sbase + (ck % 3) * STAGE;
        uint32_t sBb = sAb + ASTAGE;
        #pragma unroll
        for (int ks = 0; ks < 4; ks++) {
            const uint32_t c = (uint32_t)(ks * 2 + lch);
            uint32_t af[MT][4];
            #pragma unroll
            for (int mt = 0; mt < MT; mt++)
                LDSM_X4(af[mt][0], af[mt][1], af[mt][2], af[mt][3],
                        sAb + aro[mt] + ((c ^ arx[mt]) << 4));
            uint32_t bf[4][2];
            #pragma unroll
            for (int h = 0; h < 2; h++) {
                uint32_t t0, t1, t2, t3;
                LDSM_X4(t0, t1, t2, t3, sBb + bro[h] + ((c ^ brx[h]) << 4));
                bf[h * 2 + 0][0] = t0; bf[h * 2 + 0][1] = t2;
                bf[h * 2 + 1][0] = t1; bf[h * 2 + 1][1] = t3;
            }
            #pragma unroll
            for (int mt = 0; mt < MT; mt++)
                #pragma unroll
                for (int nt = 0; nt < 4; nt++)
                    mma16816(acc[mt][nt], af[mt], bf[nt]);
        }
    }
    __syncthreads();

    // ---- C write + fused score partials ----
    float ps[MT][4];
    #pragma unroll
    for (int mt = 0; mt < MT; mt++) {
        int gr0 = bm * MROWS + wm + mt * 16 + (lane >> 2);
        float pl0 = 0.f, pr0 = 0.f, pl1 = 0.f, pr1 = 0.f;
        #pragma unroll
        for (int nt = 0; nt < 4; nt++) {
            int col = wn + nt * 8 + (lane & 3) * 2;
            int gc = bn * 128 + col;
            if (gr0 < M)
                *(float2*)(C + (size_t)gr0 * NCOLS + gc) =
                    make_float2(acc[mt][nt][0], acc[mt][nt][1]);
            if (gr0 + 8 < M)
                *(float2*)(C + (size_t)(gr0 + 8) * NCOLS + gc) =
                    make_float2(acc[mt][nt][2], acc[mt][nt][3]);
            float a0 = al[gc], a1 = al[gc + 1];
            float b0 = ar[gc], b1 = ar[gc + 1];
            pl0 += acc[mt][nt][0] * a0 + acc[mt][nt][1] * a1;
            pr0 += acc[mt][nt][0] * b0 + acc[mt][nt][1] * b1;
            pl1 += acc[mt][nt][2] * a0 + acc[mt][nt][3] * a1;
            pr1 += acc[mt][nt][2] * b0 + acc[mt][nt][3] * b1;
        }
        #pragma unroll
        for (int o = 1; o <= 2; o <<= 1) {
            pl0 += __shfl_xor_sync(0xffffffffu, pl0, o);
            pr0 += __shfl_xor_sync(0xffffffffu, pr0, o);
            pl1 += __shfl_xor_sync(0xffffffffu, pl1, o);
            pr1 += __shfl_xor_sync(0xffffffffu, pr1, o);
        }
        ps[mt][0] = pl0; ps[mt][1] = pr0; ps[mt][2] = pl1; ps[mt][3] = pr1;
    }
    __syncthreads();
    float (*s_sl)[4] = (float(*)[4])smem;
    float (*s_sr)[4] = (float(*)[4])(smem + MROWS * 16);
    int wn4 = wid >> 1;
    if ((lane & 3) == 0) {
        #pragma unroll
        for (int mt = 0; mt < MT; mt++) {
            int lr0 = wm + mt * 16 + (lane >> 2);
            s_sl[lr0][wn4] = ps[mt][0];
            s_sr[lr0][wn4] = ps[mt][1];
            s_sl[lr0 + 8][wn4] = ps[mt][2];
            s_sr[lr0 + 8][wn4] = ps[mt][3];
        }
    }
    __syncthreads();
    if (tid < MROWS) {
        int row = bm * MROWS + tid;
        if (row < M) {
            float sl = s_sl[tid][0] + s_sl[tid][1] + s_sl[tid][2] + s_sl[tid][3];
            float sr = s_sr[tid][0] + s_sr[tid][1] + s_sr[tid][2] + s_sr[tid][3];
            el[row * st + bn] = sl;
            er[row * st + bn] = sr;
        }
    }
}

// ---------------- merged prep: fp16 conversions ----------------
__global__ void prep_all(const float* __restrict__ feats, const float* __restrict__ W1,
                         const float* __restrict__ W2, __half* __restrict__ a1,
                         __half* __restrict__ b1, __half* __restrict__ b2) {
    int i = blockIdx.x * blockDim.x + threadIdx.x;
    const int SA = NN_NODES * FF;
    const int S1 = 384 * 128;
    const int S2 = 128 * 384;
    if (i < SA) {
        a1[i] = __float2half_rn(feats[i]);
    } else if (i < SA + S1) {  // B1 = fp16(W1^T) [384, 128]
        int j = i - SA;
        int n = j >> 7, k = j & 127;
        b1[j] = __float2half_rn(W1[k * 384 + n]);
    } else if (i < SA + S1 + S2) {  // B2 = fp16(W2^T) [128, 384]
        int j = i - SA - S1;
        int n = j / 384, k = j % 384;
        b2[j] = __float2half_rn(W2[k * 128 + n]);
    }
}

// ---------------- CSR build ----------------
__global__ void zero_counts_k(int* row) {
    int i = blockIdx.x * blockDim.x + threadIdx.x;
    if (i <= NN_NODES) row[i] = 0;
}
__global__ void count_k(const int* __restrict__ dst, int* row) {
    int e = blockIdx.x * blockDim.x + threadIdx.x;
    if (e < EE_EDGES) atomicAdd(&row[dst[e]], 1);
}
__global__ void scan_block_k(int* __restrict__ row, int* __restrict__ bsums, int n) {
    __shared__ int sm[512];
    int i = blockIdx.x * 512 + threadIdx.x;
    int v = (i < n) ? row[i] : 0;
    sm[threadIdx.x] = v;
    __syncthreads();
    #pragma unroll
    for (int off = 1; off < 512; off <<= 1) {
        int t = (threadIdx.x >= off) ? sm[threadIdx.x - off] : 0;
        __syncthreads();
        sm[threadIdx.x] += t;
        __syncthreads();
    }
    int incl = sm[threadIdx.x];
    if (i < n) row[i] = incl - v;
    if (threadIdx.x == 511) bsums[blockIdx.x] = incl;
}
__global__ void scan_add_k(int* __restrict__ row, const int* __restrict__ bsums,
                           int* __restrict__ cursor, int n, int nb) {
    __shared__ int sb[65];
    int tid = threadIdx.x;
    if (tid == 0) sb[0] = 0;
    if (tid < 64) {
        int v = (tid < nb) ? bsums[tid] : 0;
        int lane = tid & 31;
        #pragma unroll
        for (int o = 1; o < 32; o <<= 1) {
            int t = __shfl_up_sync(0xffffffffu, v, o);
            if (lane >= o) v += t;
        }
        sb[tid + 1] = v;
    }
    __syncthreads();
    if (tid >= 32 && tid < 64) sb[tid + 1] += sb[32];
    __syncthreads();
    int i = blockIdx.x * blockDim.x + tid;
    if (i < n) {
        int v = row[i] + sb[i >> 9];
        row[i] = v;
        cursor[i] = v;
    }
    if (i == 0) row[n] = EE_EDGES;
}
__global__ void scatter_k(const int* __restrict__ src, const int* __restrict__ dst,
                          int* cursor, int* __restrict__ srcp) {
    int e = blockIdx.x * blockDim.x + threadIdx.x;
    if (e < EE_EDGES) {
        int p = atomicAdd(&cursor[dst[e]], 1);
        srcp[p] = src[e];
    }
}

// ---------------- aggregation, fp32 gathers, inline exp-weights: warp per (dst, head) ----------------
template <int HEADS, int ST, bool FP16OUT>
__global__ void agg_k(const float* __restrict__ hfeat, const float* __restrict__ el,
                      const float* __restrict__ er, const float* __restrict__ bias,
                      const int* __restrict__ row, const int* __restrict__ srcp,
                      float* __restrict__ out, __half* __restrict__ ocat) {
    int wg = (blockIdx.x * blockDim.x + threadIdx.x) >> 5;
    int lane = threadIdx.x & 31;
    if (wg >= NN_NODES * HEADS) return;
    int d = wg / HEADS, h = wg - d * HEADS;
    int s0 = row[d], s1 = row[d + 1];
    float erd = er[d * ST + h];

    float4 acc = make_float4(0.f, 0.f, 0.f, 0.f);
    float den = 0.f;
    #pragma unroll 2
    for (int i = s0; i < s1; ++i) {
        int s = srcp[i];
        float e = el[s * ST + h] + erd;
        e = (e > 0.f) ? e : 0.2f * e;
        float wt = __expf(e);
        den += wt;
        float4 v = *(const float4*)(hfeat + (size_t)s * (HEADS * 128) + h * 128 + lane * 4);
        acc.x += wt * v.x;
        acc.y += wt * v.y;
        acc.z += wt * v.z;
        acc.w += wt * v.w;
    }
    float inv = 1.0f / den;
    float4 b4 = *(const float4*)(bias + h * 128 + lane * 4);
    float r[4] = {acc.x * inv + b4.x, acc.y * inv + b4.y,
                  acc.z * inv + b4.z, acc.w * inv + b4.w};
    if (FP16OUT) {
        __half hv[4];
        #pragma unroll
        for (int q = 0; q < 4; q++) hv[q] = __float2half_rn(r[q]);
        size_t base = (size_t)d * 384 + h * 128 + lane * 4;
        *(uint2*)(ocat + base) = *(uint2*)hv;
    } else {
        *(float4*)(out + (size_t)d * (HEADS * 128) + h * 128 + lane * 4) =
            make_float4(r[0], r[1], r[2], r[3]);
    }
}

// ---------------- launch ----------------
static inline int cdiv(int a, int b) { return (a + b - 1) / b; }

extern "C" void kernel_launch(void* const* d_in, const int* in_sizes, int n_in,
                              void* d_out, int out_size) {
    const float* feats   = (const float*)d_in[0];
    const float* W1      = (const float*)d_in[1];
    const float* attn_l1 = (const float*)d_in[2];
    const float* attn_r1 = (const float*)d_in[3];
    const float* bias1   = (const float*)d_in[4];
    const float* W2      = (const float*)d_in[5];
    const float* attn_l2 = (const float*)d_in[6];
    const float* attn_r2 = (const float*)d_in[7];
    const float* bias2   = (const float*)d_in[8];
    const int*   src     = (const int*)d_in[9];
    const int*   dst     = (const int*)d_in[10];
    float* out = (float*)d_out;

    float *h1, *h2, *el1, *er1, *el2, *er2;
    int *row, *cursor, *srcp, *bsums;
    __half *a1cat, *a2cat, *b1cat, *b2cat;
    cudaGetSymbolAddress((void**)&h1, g_h1);
    cudaGetSymbolAddress((void**)&h2, g_h2);
    cudaGetSymbolAddress((void**)&el1, g_el1);
    cudaGetSymbolAddress((void**)&er1, g_er1);
    cudaGetSymbolAddress((void**)&el2, g_el2);
    cudaGetSymbolAddress((void**)&er2, g_er2);
    cudaGetSymbolAddress((void**)&row, g_row);
    cudaGetSymbolAddress((void**)&cursor, g_cursor);
    cudaGetSymbolAddress((void**)&srcp, g_srcp);
    cudaGetSymbolAddress((void**)&bsums, g_bsums);
    cudaGetSymbolAddress((void**)&a1cat, g_a1cat);
    cudaGetSymbolAddress((void**)&a2cat, g_a2cat);
    cudaGetSymbolAddress((void**)&b1cat, g_b1cat);
    cudaGetSymbolAddress((void**)&b2cat, g_b2cat);

    static cudaStream_t s2 = nullptr;
    static cudaEvent_t evFork = nullptr, evJoin = nullptr;
    static bool attrDone = false;
    if (!s2) {
        cudaStreamCreateWithFlags(&s2, cudaStreamNonBlocking);
        cudaEventCreateWithFlags(&evFork, cudaEventDisableTiming);
        cudaEventCreateWithFlags(&evJoin, cudaEventDisableTiming);
    }
    if (!attrDone) {
        cudaFuncSetAttribute(gemm_mma<128>, cudaFuncAttributeMaxDynamicSharedMemorySize,
                             3 * (128 * 128 + 16384));
        cudaFuncSetAttribute(gemm_mma<64>, cudaFuncAttributeMaxDynamicSharedMemorySize,
                             3 * (64 * 128 + 16384));
        attrDone = true;
    }

    const int nb = cdiv(NN_NODES, 512);

    // fork CSR head on side stream
    cudaEventRecord(evFork, 0);
    cudaStreamWaitEvent(s2, evFork, 0);
    zero_counts_k<<<cdiv(NN_NODES + 1, 256), 256, 0, s2>>>(row);             // 1
    count_k<<<cdiv(EE_EDGES, 256), 256, 0, s2>>>(dst, row);                  // 2
    prep_all<<<cdiv(NN_NODES * FF + 2 * 384 * 128, 256), 256>>>(             // 3
        feats, W1, W2, a1cat, b1cat, b2cat);
    {
        dim3 grid(cdiv(NN_NODES, 128), 3);
        gemm_mma<128><<<grid, 256, 3 * (128 * 128 + 16384)>>>(               // 4 (profiled)
            a1cat, b1cat, h1, NN_NODES, 128, 384, attn_l1, attn_r1, el1, er1, 4);
    }
    scan_block_k<<<nb, 512, 0, s2>>>(row, bsums, NN_NODES);                  // 5
    scan_add_k<<<cdiv(NN_NODES, 256), 256, 0, s2>>>(row, bsums, cursor, NN_NODES, nb); // 6
    scatter_k<<<cdiv(EE_EDGES, 256), 256, 0, s2>>>(src, dst, cursor, srcp);  // 7
    cudaEventRecord(evJoin, s2);

    cudaStreamWaitEvent(0, evJoin, 0);
    agg_k<HH1, 4, true><<<cdiv(NN_NODES * HH1 * 32, 256), 256>>>(            // 8
        h1, el1, er1, bias1, row, srcp, nullptr, a2cat);

    {
        dim3 grid(cdiv(NN_NODES, 64), 1);
        gemm_mma<64><<<grid, 256, 3 * (64 * 128 + 16384)>>>(                 // 9
            a2cat, b2cat, h2, NN_NODES, 384, 128, attn_l2, attn_r2, el2, er2, 1);
    }
    agg_k<1, 1, false><<<cdiv(NN_NODES * 32, 256), 256>>>(                   // 10
        h2, el2, er2, bias2, row, srcp, out, nullptr);
}

// round 13
// speedup vs baseline: 1.2370x; 1.0108x over previous
#include <cuda_runtime.h>
#include <cuda_fp16.h>
#include <math_constants.h>
#include <cstdint>

#define NN_NODES 20000
#define EE_EDGES 320000
#define FF 128
#define HH1 3

// ---------------- scratch (static device allocations) ----------------
__device__ float g_h2[NN_NODES * FF];          // layer2 projected feats fp32
__device__ float g_el1[NN_NODES * 4];          // stride 4 (3 heads + pad)
__device__ float g_er1[NN_NODES * 4];
__device__ float g_el2[NN_NODES];
__device__ float g_er2[NN_NODES];
__device__ float g_wproj[1536];                // wl1[384] | wr1[384] | w2l[384] | w2r[384]
__device__ int   g_row[NN_NODES + 1];
__device__ int   g_cursor[NN_NODES];
__device__ int   g_srcp[EE_EDGES];
__device__ int   g_bsums[64];
__device__ __align__(16) __half g_a1cat[NN_NODES * 128];            // fp16(x) [N,128]
__device__ __align__(16) __half g_xagg[(size_t)NN_NODES * 384];     // aggregated x per head
__device__ __align__(16) __half g_a2cat[(size_t)NN_NODES * 384];    // rst1 fp16 [N,384]
__device__ __align__(16) __half g_b1cat[384 * 128];                 // fp16(W1^T)
__device__ __align__(16) __half g_b2cat[128 * 384];                 // fp16(W2^T)

// ---------------- helpers ----------------
__device__ __forceinline__ uint32_t smem_u32(const void* p) {
    uint32_t a;
    asm("{ .reg .u64 t; cvta.to.shared.u64 t, %1; cvt.u32.u64 %0, t; }" : "=r"(a) : "l"(p));
    return a;
}
#define LDSM_X4(r0, r1, r2, r3, addr) \
    asm volatile("ldmatrix.sync.aligned.m8n8.x4.shared.b16 {%0,%1,%2,%3}, [%4];" \
                 : "=r"(r0), "=r"(r1), "=r"(r2), "=r"(r3) : "r"(addr))

__device__ __forceinline__ void mma16816(float* d, const uint32_t* a, const uint32_t* b) {
    asm volatile(
        "mma.sync.aligned.m16n8k16.row.col.f32.f16.f16.f32 "
        "{%0,%1,%2,%3}, {%4,%5,%6,%7}, {%8,%9}, {%0,%1,%2,%3};"
        : "+f"(d[0]), "+f"(d[1]), "+f"(d[2]), "+f"(d[3])
        : "r"(a[0]), "r"(a[1]), "r"(a[2]), "r"(a[3]), "r"(b[0]), "r"(b[1]));
}
__device__ __forceinline__ void cp16(uint32_t saddr, const void* g, uint32_t sz) {
    asm volatile("cp.async.cg.shared.global [%0], [%1], 16, %2;"
                 :: "r"(saddr), "l"(g), "r"(sz) : "memory");
}
#define CP_COMMIT() asm volatile("cp.async.commit_group;" ::: "memory")
#define CP_WAIT1()  asm volatile("cp.async.wait_group 1;" ::: "memory")

// ---------------- fp16 mma.sync GEMM, 3-stage cp.async ----------------
// C[M,NCOLS] = A'[M,K] @ B[NCOLS,K]^T; A row = A + gr*Ald + bn*aoffBn (per-head A slice).
// Output: Ch (fp16, +bias) if non-null, else Cf (fp32, no bias).
template <int MROWS>
__global__ __launch_bounds__(256) void gemm_mma(const __half* __restrict__ A, int Ald,
                                                int aoffBn,
                                                const __half* __restrict__ B, int K,
                                                float* __restrict__ Cf,
                                                __half* __restrict__ Ch,
                                                const float* __restrict__ bias,
                                                int M, int NCOLS) {
    extern __shared__ __align__(16) uint8_t smem[];
    constexpr int ASTAGE = MROWS * 128;
    constexpr int STAGE = ASTAGE + 16384;
    constexpr int MT = MROWS / 32;
    constexpr int AP = MROWS / 32;
    const int tid = threadIdx.x, lane = tid & 31, wid = tid >> 5;
    const int bm = blockIdx.x, bn = blockIdx.y;
    const int wm = (wid & 1) * (MROWS / 2), wn = (wid >> 1) * 32;
    const uint32_t sbase = smem_u32(smem);

    float acc[MT][4][4];
    #pragma unroll
    for (int i = 0; i < MT; i++)
        #pragma unroll
        for (int j = 0; j < 4; j++)
            #pragma unroll
            for (int q = 0; q < 4; q++) acc[i][j][q] = 0.f;

    const int lrow = ((lane >> 3) & 1) * 8 + (lane & 7);
    const int lch = lane >> 4;

    uint32_t aro[MT], arx[MT], bro[2], brx[2];
    #pragma unroll
    for (int mt = 0; mt < MT; mt++) {
        int r = wm + mt * 16 + lrow;
        aro[mt] = (uint32_t)(r * 128);
        arx[mt] = (uint32_t)(r & 7);
    }
    #pragma unroll
    for (int h = 0; h < 2; h++) {
        int r = wn + h * 16 + lrow;
        bro[h] = (uint32_t)(r * 128);
        brx[h] = (uint32_t)(r & 7);
    }

    int alr[AP], alc[AP];
    uint32_t aso[AP];
    #pragma unroll
    for (int p = 0; p < AP; p++) {
        int g = tid + p * 256;
        alr[p] = g >> 3;
        alc[p] = g & 7;
        aso[p] = (uint32_t)(alr[p] * 128 + ((alc[p] ^ (alr[p] & 7)) << 4));
    }
    int blr[4], blc[4];
    uint32_t bso[4];
    #pragma unroll
    for (int p = 0; p < 4; p++) {
        int g = tid + p * 256;
        blr[p] = g >> 3;
        blc[p] = g & 7;
        bso[p] = (uint32_t)(blr[p] * 128 + ((blc[p] ^ (blr[p] & 7)) << 4));
    }

    const __half* Ab = A + bn * aoffBn;
    auto issue = [&](int stage, int kn) {
        uint32_t sa = sbase + stage * STAGE;
        uint32_t sb = sa + ASTAGE;
        #pragma unroll
        for (int p = 0; p < AP; p++) {
            int gr = bm * MROWS + alr[p];
            cp16(sa + aso[p], Ab + (size_t)gr * Ald + kn + alc[p] * 8,
                 (gr < M) ? 16u : 0u);
        }
        #pragma unroll
        for (int p = 0; p < 4; p++)
            cp16(sb + bso[p], B + (size_t)(bn * 128 + blr[p]) * K + kn + blc[p] * 8, 16u);
        CP_COMMIT();
    };

    issue(0, 0);
    if (K > 64) issue(1, 64);
    else CP_COMMIT();

    const int nchunks = K >> 6;
    for (int ck = 0; ck < nchunks; ck++) {
        CP_WAIT1();
        __syncthreads();
        if (ck + 2 < nchunks) issue((ck + 2) % 3, (ck + 2) * 64);
        else CP_COMMIT();
        uint32_t sAb = sbase + (ck % 3) * STAGE;
        uint32_t sBb = sAb + ASTAGE;
        #pragma unroll
        for (int ks = 0; ks < 4; ks++) {
            const uint32_t c = (uint32_t)(ks * 2 + lch);
            uint32_t af[MT][4];
            #pragma unroll
            for (int mt = 0; mt < MT; mt++)
                LDSM_X4(af[mt][0], af[mt][1], af[mt][2], af[mt][3],
                        sAb + aro[mt] + ((c ^ arx[mt]) << 4));
            uint32_t bf[4][2];
            #pragma unroll
            for (int h = 0; h < 2; h++) {
                uint32_t t0, t1, t2, t3;
                LDSM_X4(t0, t1, t2, t3, sBb + bro[h] + ((c ^ brx[h]) << 4));
                bf[h * 2 + 0][0] = t0; bf[h * 2 + 0][1] = t2;
                bf[h * 2 + 1][0] = t1; bf[h * 2 + 1][1] = t3;
            }
            #pragma unroll
            for (int mt = 0; mt < MT; mt++)
                #pragma unroll
                for (int nt = 0; nt < 4; nt++)
                    mma16816(acc[mt][nt], af[mt], bf[nt]);
        }
    }

    // ---- epilogue: plain writes (fp16+bias or fp32) ----
    #pragma unroll
    for (int mt = 0; mt < MT; mt++) {
        int gr0 = bm * MROWS + wm + mt * 16 + (lane >> 2);
        #pragma unroll
        for (int nt = 0; nt < 4; nt++) {
            int col = wn + nt * 8 + (lane & 3) * 2;
            int gc = bn * 128 + col;
            if (Ch) {
                float b0 = bias[gc], b1v = bias[gc + 1];
                if (gr0 < M)
                    *(__half2*)(Ch + (size_t)gr0 * NCOLS + gc) =
                        __floats2half2_rn(acc[mt][nt][0] + b0, acc[mt][nt][1] + b1v);
                if (gr0 + 8 < M)
                    *(__half2*)(Ch + (size_t)(gr0 + 8) * NCOLS + gc) =
                        __floats2half2_rn(acc[mt][nt][2] + b0, acc[mt][nt][3] + b1v);
            } else {
                if (gr0 < M)
                    *(float2*)(Cf + (size_t)gr0 * NCOLS + gc) =
                        make_float2(acc[mt][nt][0], acc[mt][nt][1]);
                if (gr0 + 8 < M)
                    *(float2*)(Cf + (size_t)(gr0 + 8) * NCOLS + gc) =
                        make_float2(acc[mt][nt][2], acc[mt][nt][3]);
            }
        }
    }
}

// ---------------- prep: fp16 conversions ----------------
__global__ void prep_all(const float* __restrict__ feats, const float* __restrict__ W1,
                         const float* __restrict__ W2, __half* __restrict__ a1,
                         __half* __restrict__ b1, __half* __restrict__ b2) {
    int i = blockIdx.x * blockDim.x + threadIdx.x;
    const int SA = NN_NODES * FF;
    const int S1 = 384 * 128;
    const int S2 = 128 * 384;
    if (i < SA) {
        a1[i] = __float2half_rn(feats[i]);
    } else if (i < SA + S1) {
        int j = i - SA;
        int n = j >> 7, k = j & 127;
        b1[j] = __float2half_rn(W1[k * 384 + n]);
    } else if (i < SA + S1 + S2) {
        int j = i - SA - S1;
        int n = j / 384, k = j % 384;
        b2[j] = __float2half_rn(W2[k * 128 + n]);
    }
}

// ---------------- proj: attention vectors pulled through the weights ----------------
// wl1[h*128+k] = sum_j W1[k, h*128+j] al1[h,j]; w2l[k] = sum_j W2[k,j] al2[j]; same for r.
__global__ void proj_k(const float* __restrict__ W1, const float* __restrict__ W2,
                       const float* __restrict__ al1, const float* __restrict__ ar1,
                       const float* __restrict__ al2, const float* __restrict__ ar2,
                       float* __restrict__ wp) {
    int w = (blockIdx.x * blockDim.x + threadIdx.x) >> 5;
    int lane = threadIdx.x & 31;
    if (w >= 1536) return;
    const float* vec;
    const float* att;
    if (w < 768) {
        int j = (w < 384) ? w : w - 384;
        int h = j >> 7, k = j & 127;
        vec = W1 + k * 384 + h * 128;
        att = ((w < 384) ? al1 : ar1) + h * 128;
    } else {
        int k = (w < 1152) ? (w - 768) : (w - 1152);
        vec = W2 + k * 128;
        att = (w < 1152) ? al2 : ar2;
    }
    float4 a = *(const float4*)(vec + lane * 4);
    float4 b = *(const float4*)(att + lane * 4);
    float s = a.x * b.x + a.y * b.y + a.z * b.z + a.w * b.w;
    #pragma unroll
    for (int o = 16; o; o >>= 1) s += __shfl_xor_sync(0xffffffffu, s, o);
    if (lane == 0) wp[w] = s;
}

// ---------------- score1: el1/er1 from raw x (one warp per node) ----------------
__global__ void score1_k(const float* __restrict__ feats, const float* __restrict__ wp,
                         float* __restrict__ el, float* __restrict__ er) {
    int n = (blockIdx.x * blockDim.x + threadIdx.x) >> 5;
    int lane = threadIdx.x & 31;
    if (n >= NN_NODES) return;
    float4 x = *(const float4*)(feats + (size_t)n * 128 + lane * 4);
    float sl[3], sr[3];
    #pragma unroll
    for (int h = 0; h < 3; h++) {
        float4 a = *(const float4*)(wp + h * 128 + lane * 4);
        float4 b = *(const float4*)(wp + 384 + h * 128 + lane * 4);
        sl[h] = x.x * a.x + x.y * a.y + x.z * a.z + x.w * a.w;
        sr[h] = x.x * b.x + x.y * b.y + x.z * b.z + x.w * b.w;
    }
    #pragma unroll
    for (int h = 0; h < 3; h++)
        #pragma unroll
        for (int o = 16; o; o >>= 1) {
            sl[h] += __shfl_xor_sync(0xffffffffu, sl[h], o);
            sr[h] += __shfl_xor_sync(0xffffffffu, sr[h], o);
        }
    if (lane == 0) {
        #pragma unroll
        for (int h = 0; h < 3; h++) {
            el[n * 4 + h] = sl[h];
            er[n * 4 + h] = sr[h];
        }
    }
}

// ---------------- score2: el2/er2 from rst1 fp16 (one warp per node) ----------------
__global__ void score2_k(const __half* __restrict__ a2, const float* __restrict__ wp,
                         float* __restrict__ el, float* __restrict__ er) {
    int n = (blockIdx.x * blockDim.x + threadIdx.x) >> 5;
    int lane = threadIdx.x & 31;
    if (n >= NN_NODES) return;
    float sl = 0.f, sr = 0.f;
    #pragma unroll
    for (int seg = 0; seg < 3; seg++) {
        int k0 = seg * 128 + lane * 4;
        uint2 raw = *(const uint2*)(a2 + (size_t)n * 384 + k0);
        float2 v0 = __half22float2(*(__half2*)&raw.x);
        float2 v1 = __half22float2(*(__half2*)&raw.y);
        float4 a = *(const float4*)(wp + 768 + k0);
        float4 b = *(const float4*)(wp + 1152 + k0);
        sl += v0.x * a.x + v0.y * a.y + v1.x * a.z + v1.y * a.w;
        sr += v0.x * b.x + v0.y * b.y + v1.x * b.z + v1.y * b.w;
    }
    #pragma unroll
    for (int o = 16; o; o >>= 1) {
        sl += __shfl_xor_sync(0xffffffffu, sl, o);
        sr += __shfl_xor_sync(0xffffffffu, sr, o);
    }
    if (lane == 0) { el[n] = sl; er[n] = sr; }
}

// ---------------- CSR build ----------------
__global__ void zero_counts_k(int* row) {
    int i = blockIdx.x * blockDim.x + threadIdx.x;
    if (i <= NN_NODES) row[i] = 0;
}
__global__ void count_k(const int* __restrict__ dst, int* row) {
    int e = blockIdx.x * blockDim.x + threadIdx.x;
    if (e < EE_EDGES) atomicAdd(&row[dst[e]], 1);
}
__global__ void scan_block_k(int* __restrict__ row, int* __restrict__ bsums, int n) {
    __shared__ int sm[512];
    int i = blockIdx.x * 512 + threadIdx.x;
    int v = (i < n) ? row[i] : 0;
    sm[threadIdx.x] = v;
    __syncthreads();
    #pragma unroll
    for (int off = 1; off < 512; off <<= 1) {
        int t = (threadIdx.x >= off) ? sm[threadIdx.x - off] : 0;
        __syncthreads();
        sm[threadIdx.x] += t;
        __syncthreads();
    }
    int incl = sm[threadIdx.x];
    if (i < n) row[i] = incl - v;
    if (threadIdx.x == 511) bsums[blockIdx.x] = incl;
}
__global__ void scan_add_k(int* __restrict__ row, const int* __restrict__ bsums,
                           int* __restrict__ cursor, int n, int nb) {
    __shared__ int sb[65];
    int tid = threadIdx.x;
    if (tid == 0) sb[0] = 0;
    if (tid < 64) {
        int v = (tid < nb) ? bsums[tid] : 0;
        int lane = tid & 31;
        #pragma unroll
        for (int o = 1; o < 32; o <<= 1) {
            int t = __shfl_up_sync(0xffffffffu, v, o);
            if (lane >= o) v += t;
        }
        sb[tid + 1] = v;
    }
    __syncthreads();
    if (tid >= 32 && tid < 64) sb[tid + 1] += sb[32];
    __syncthreads();
    int i = blockIdx.x * blockDim.x + tid;
    if (i < n) {
        int v = row[i] + sb[i >> 9];
        row[i] = v;
        cursor[i] = v;
    }
    if (i == 0) row[n] = EE_EDGES;
}
__global__ void scatter_k(const int* __restrict__ src, const int* __restrict__ dst,
                          int* cursor, int* __restrict__ srcp) {
    int e = blockIdx.x * blockDim.x + threadIdx.x;
    if (e < EE_EDGES) {
        int p = atomicAdd(&cursor[dst[e]], 1);
        srcp[p] = src[e];
    }
}

// ---------------- agg1: aggregate 128-dim fp16 x for all 3 heads; warp per dst ----------------
__global__ void agg1_k(const __half* __restrict__ x, const float* __restrict__ el,
                       const float* __restrict__ er, const int* __restrict__ row,
                       const int* __restrict__ srcp, __half* __restrict__ xagg) {
    int d = (blockIdx.x * blockDim.x + threadIdx.x) >> 5;
    int lane = threadIdx.x & 31;
    if (d >= NN_NODES) return;
    int s0 = row[d], s1 = row[d + 1];
    float4 erv = *(const float4*)(er + d * 4);

    float4 acc[3];
    float den[3];
    #pragma unroll
    for (int h = 0; h < 3; h++) {
        acc[h] = make_float4(0.f, 0.f, 0.f, 0.f);
        den[h] = 0.f;
    }
    for (int i = s0; i < s1; ++i) {
        int s = srcp[i];
        float4 elv = *(const float4*)(el + s * 4);
        uint2 raw = *(const uint2*)(x + (size_t)s * 128 + lane * 4);
        float2 v0 = __half22float2(*(__half2*)&raw.x);
        float2 v1 = __half22float2(*(__half2*)&raw.y);
        float e0 = elv.x + erv.x; e0 = (e0 > 0.f) ? e0 : 0.2f * e0;
        float e1 = elv.y + erv.y; e1 = (e1 > 0.f) ? e1 : 0.2f * e1;
        float e2 = elv.z + erv.z; e2 = (e2 > 0.f) ? e2 : 0.2f * e2;
        float w0 = __expf(e0), w1 = __expf(e1), w2 = __expf(e2);
        den[0] += w0; den[1] += w1; den[2] += w2;
        acc[0].x += w0 * v0.x; acc[0].y += w0 * v0.y; acc[0].z += w0 * v1.x; acc[0].w += w0 * v1.y;
        acc[1].x += w1 * v0.x; acc[1].y += w1 * v0.y; acc[1].z += w1 * v1.x; acc[1].w += w1 * v1.y;
        acc[2].x += w2 * v0.x; acc[2].y += w2 * v0.y; acc[2].z += w2 * v1.x; acc[2].w += w2 * v1.y;
    }
    #pragma unroll
    for (int h = 0; h < 3; h++) {
        float inv = 1.0f / den[h];
        __half2 o0 = __floats2half2_rn(acc[h].x * inv, acc[h].y * inv);
        __half2 o1 = __floats2half2_rn(acc[h].z * inv, acc[h].w * inv);
        uint2 pack;
        pack.x = *(uint32_t*)&o0;
        pack.y = *(uint32_t*)&o1;
        *(uint2*)(xagg + (size_t)d * 384 + h * 128 + lane * 4) = pack;
    }
}

// ---------------- agg2: gather fp32 h2 (1 head), +bias; warp per dst ----------------
__global__ void agg2_k(const float* __restrict__ hfeat, const float* __restrict__ el,
                       const float* __restrict__ er, const float* __restrict__ bias,
                       const int* __restrict__ row, const int* __restrict__ srcp,
                       float* __restrict__ out) {
    int d = (blockIdx.x * blockDim.x + threadIdx.x) >> 5;
    int lane = threadIdx.x & 31;
    if (d >= NN_NODES) return;
    int s0 = row[d], s1 = row[d + 1];
    float erd = er[d];

    float4 acc = make_float4(0.f, 0.f, 0.f, 0.f);
    float den = 0.f;
    #pragma unroll 2
    for (int i = s0; i < s1; ++i) {
        int s = srcp[i];
        float e = el[s] + erd;
        e = (e > 0.f) ? e : 0.2f * e;
        float wt = __expf(e);
        den += wt;
        float4 v = *(const float4*)(hfeat + (size_t)s * 128 + lane * 4);
        acc.x += wt * v.x;
        acc.y += wt * v.y;
        acc.z += wt * v.z;
        acc.w += wt * v.w;
    }
    float inv = 1.0f / den;
    float4 b4 = *(const float4*)(bias + lane * 4);
    *(float4*)(out + (size_t)d * 128 + lane * 4) =
        make_float4(acc.x * inv + b4.x, acc.y * inv + b4.y,
                    acc.z * inv + b4.z, acc.w * inv + b4.w);
}

// ---------------- launch ----------------
static inline int cdiv(int a, int b) { return (a + b - 1) / b; }

extern "C" void kernel_launch(void* const* d_in, const int* in_sizes, int n_in,
                              void* d_out, int out_size) {
    const float* feats   = (const float*)d_in[0];
    const float* W1      = (const float*)d_in[1];
    const float* attn_l1 = (const float*)d_in[2];
    const float* attn_r1 = (const float*)d_in[3];
    const float* bias1   = (const float*)d_in[4];
    const float* W2      = (const float*)d_in[5];
    const float* attn_l2 = (const float*)d_in[6];
    const float* attn_r2 = (const float*)d_in[7];
    const float* bias2   = (const float*)d_in[8];
    const int*   src     = (const int*)d_in[9];
    const int*   dst     = (const int*)d_in[10];
    float* out = (float*)d_out;

    float *h2, *el1, *er1, *el2, *er2, *wp;
    int *row, *cursor, *srcp, *bsums;
    __half *a1cat, *xagg, *a2cat, *b1cat, *b2cat;
    cudaGetSymbolAddress((void**)&h2, g_h2);
    cudaGetSymbolAddress((void**)&el1, g_el1);
    cudaGetSymbolAddress((void**)&er1, g_er1);
    cudaGetSymbolAddress((void**)&el2, g_el2);
    cudaGetSymbolAddress((void**)&er2, g_er2);
    cudaGetSymbolAddress((void**)&wp, g_wproj);
    cudaGetSymbolAddress((void**)&row, g_row);
    cudaGetSymbolAddress((void**)&cursor, g_cursor);
    cudaGetSymbolAddress((void**)&srcp, g_srcp);
    cudaGetSymbolAddress((void**)&bsums, g_bsums);
    cudaGetSymbolAddress((void**)&a1cat, g_a1cat);
    cudaGetSymbolAddress((void**)&xagg, g_xagg);
    cudaGetSymbolAddress((void**)&a2cat, g_a2cat);
    cudaGetSymbolAddress((void**)&b1cat, g_b1cat);
    cudaGetSymbolAddress((void**)&b2cat, g_b2cat);

    static cudaStream_t s2 = nullptr;
    static cudaEvent_t evFork = nullptr, evJoin = nullptr;
    static bool attrDone = false;
    if (!s2) {
        cudaStreamCreateWithFlags(&s2, cudaStreamNonBlocking);
        cudaEventCreateWithFlags(&evFork, cudaEventDisableTiming);
        cudaEventCreateWithFlags(&evJoin, cudaEventDisableTiming);
    }
    if (!attrDone) {
        cudaFuncSetAttribute(gemm_mma<128>, cudaFuncAttributeMaxDynamicSharedMemorySize,
                             3 * (128 * 128 + 16384));
        cudaFuncSetAttribute(gemm_mma<64>, cudaFuncAttributeMaxDynamicSharedMemorySize,
                             3 * (64 * 128 + 16384));
        attrDone = true;
    }

    const int nb = cdiv(NN_NODES, 512);

    // fork: CSR build on side stream (overlaps prep/proj/score1)
    cudaEventRecord(evFork, 0);
    cudaStreamWaitEvent(s2, evFork, 0);
    zero_counts_k<<<cdiv(NN_NODES + 1, 256), 256, 0, s2>>>(row);
    count_k<<<cdiv(EE_EDGES, 256), 256, 0, s2>>>(dst, row);
    scan_block_k<<<nb, 512, 0, s2>>>(row, bsums, NN_NODES);
    scan_add_k<<<cdiv(NN_NODES, 256), 256, 0, s2>>>(row, bsums, cursor, NN_NODES, nb);
    scatter_k<<<cdiv(EE_EDGES, 256), 256, 0, s2>>>(src, dst, cursor, srcp);
    cudaEventRecord(evJoin, s2);

    // main: prep + projections + layer-1 scores (no GEMM needed before aggregation!)
    prep_all<<<cdiv(NN_NODES * FF + 2 * 384 * 128, 256), 256>>>(
        feats, W1, W2, a1cat, b1cat, b2cat);
    proj_k<<<cdiv(1536 * 32, 256), 256>>>(W1, W2, attn_l1, attn_r1, attn_l2, attn_r2, wp);
    score1_k<<<cdiv(NN_NODES * 32, 256), 256>>>(feats, wp, el1, er1);

    // join: aggregate x per head, then per-head GEMM with bias -> rst1 fp16
    cudaStreamWaitEvent(0, evJoin, 0);
    agg1_k<<<cdiv(NN_NODES * 32, 256), 256>>>(a1cat, el1, er1, row, srcp, xagg);
    {
        dim3 grid(cdiv(NN_NODES, 128), 3);
        gemm_mma<128><<<grid, 256, 3 * (128 * 128 + 16384)>>>(
            xagg, 384, 128, b1cat, 128, nullptr, a2cat, bias1, NN_NODES, 384);
    }

    // layer 2: scores from rst1 directly, h2 GEMM, then aggregate h2
    score2_k<<<cdiv(NN_NODES * 32, 256), 256>>>(a2cat, wp, el2, er2);
    {
        dim3 grid(cdiv(NN_NODES, 64), 1);
        gemm_mma<64><<<grid, 256, 3 * (64 * 128 + 16384)>>>(
            a2cat, 384, 0, b2cat, 384, h2, nullptr, nullptr, NN_NODES, 128);
    }
    agg2_k<<<cdiv(NN_NODES * 32, 256), 256>>>(h2, el2, er2, bias2, row, srcp, out);
}

// round 14
// speedup vs baseline: 1.3462x; 1.0883x over previous
#include <cuda_runtime.h>
#include <cuda_fp16.h>
#include <math_constants.h>
#include <cstdint>

#define NN_NODES 20000
#define EE_EDGES 320000
#define FF 128
#define HH1 3

// ---------------- scratch (static device allocations) ----------------
__device__ float g_h2[NN_NODES * FF];
__device__ float g_el1[NN_NODES * 4];
__device__ float g_er1[NN_NODES * 4];
__device__ float g_el2[NN_NODES];
__device__ float g_er2[NN_NODES];
__device__ float g_wproj[1536];                // wl1[384] | wr1[384] | w2l[384] | w2r[384]
__device__ int   g_row[NN_NODES + 1];
__device__ int   g_cursor[NN_NODES];
__device__ int   g_srcp[EE_EDGES];
__device__ int   g_bsums[64];
__device__ __align__(16) __half g_a1cat[NN_NODES * 128];
__device__ __align__(16) __half g_xagg[(size_t)NN_NODES * 384];
__device__ __align__(16) __half g_a2cat[(size_t)NN_NODES * 384];
__device__ __align__(16) __half g_b1cat[384 * 128];
__device__ __align__(16) __half g_b2cat[128 * 384];

// ---------------- helpers ----------------
__device__ __forceinline__ uint32_t smem_u32(const void* p) {
    uint32_t a;
    asm("{ .reg .u64 t; cvta.to.shared.u64 t, %1; cvt.u32.u64 %0, t; }" : "=r"(a) : "l"(p));
    return a;
}
#define LDSM_X4(r0, r1, r2, r3, addr) \
    asm volatile("ldmatrix.sync.aligned.m8n8.x4.shared.b16 {%0,%1,%2,%3}, [%4];" \
                 : "=r"(r0), "=r"(r1), "=r"(r2), "=r"(r3) : "r"(addr))

__device__ __forceinline__ void mma16816(float* d, const uint32_t* a, const uint32_t* b) {
    asm volatile(
        "mma.sync.aligned.m16n8k16.row.col.f32.f16.f16.f32 "
        "{%0,%1,%2,%3}, {%4,%5,%6,%7}, {%8,%9}, {%0,%1,%2,%3};"
        : "+f"(d[0]), "+f"(d[1]), "+f"(d[2]), "+f"(d[3])
        : "r"(a[0]), "r"(a[1]), "r"(a[2]), "r"(a[3]), "r"(b[0]), "r"(b[1]));
}
__device__ __forceinline__ void cp16(uint32_t saddr, const void* g, uint32_t sz) {
    asm volatile("cp.async.cg.shared.global [%0], [%1], 16, %2;"
                 :: "r"(saddr), "l"(g), "r"(sz) : "memory");
}
#define CP_COMMIT() asm volatile("cp.async.commit_group;" ::: "memory")
#define CP_WAIT1()  asm volatile("cp.async.wait_group 1;" ::: "memory")

// ---------------- fp16 mma.sync GEMM, 3-stage cp.async ----------------
// C[M,NCOLS] = A'[M,K] @ B[NCOLS,K]^T; A row = A + gr*Ald + bn*aoffBn (per-head A slice).
// Output: Ch (fp16, +bias) if non-null, else Cf (fp32, no bias).
template <int MROWS>
__global__ __launch_bounds__(256) void gemm_mma(const __half* __restrict__ A, int Ald,
                                                int aoffBn,
                                                const __half* __restrict__ B, int K,
                                                float* __restrict__ Cf,
                                                __half* __restrict__ Ch,
                                                const float* __restrict__ bias,
                                                int M, int NCOLS) {
    extern __shared__ __align__(16) uint8_t smem[];
    constexpr int ASTAGE = MROWS * 128;
    constexpr int STAGE = ASTAGE + 16384;
    constexpr int MT = MROWS / 32;
    constexpr int AP = MROWS / 32;
    const int tid = threadIdx.x, lane = tid & 31, wid = tid >> 5;
    const int bm = blockIdx.x, bn = blockIdx.y;
    const int wm = (wid & 1) * (MROWS / 2), wn = (wid >> 1) * 32;
    const uint32_t sbase = smem_u32(smem);

    float acc[MT][4][4];
    #pragma unroll
    for (int i = 0; i < MT; i++)
        #pragma unroll
        for (int j = 0; j < 4; j++)
            #pragma unroll
            for (int q = 0; q < 4; q++) acc[i][j][q] = 0.f;

    const int lrow = ((lane >> 3) & 1) * 8 + (lane & 7);
    const int lch = lane >> 4;

    uint32_t aro[MT], arx[MT], bro[2], brx[2];
    #pragma unroll
    for (int mt = 0; mt < MT; mt++) {
        int r = wm + mt * 16 + lrow;
        aro[mt] = (uint32_t)(r * 128);
        arx[mt] = (uint32_t)(r & 7);
    }
    #pragma unroll
    for (int h = 0; h < 2; h++) {
        int r = wn + h * 16 + lrow;
        bro[h] = (uint32_t)(r * 128);
        brx[h] = (uint32_t)(r & 7);
    }

    int alr[AP], alc[AP];
    uint32_t aso[AP];
    #pragma unroll
    for (int p = 0; p < AP; p++) {
        int g = tid + p * 256;
        alr[p] = g >> 3;
        alc[p] = g & 7;
        aso[p] = (uint32_t)(alr[p] * 128 + ((alc[p] ^ (alr[p] & 7)) << 4));
    }
    int blr[4], blc[4];
    uint32_t bso[4];
    #pragma unroll
    for (int p = 0; p < 4; p++) {
        int g = tid + p * 256;
        blr[p] = g >> 3;
        blc[p] = g & 7;
        bso[p] = (uint32_t)(blr[p] * 128 + ((blc[p] ^ (blr[p] & 7)) << 4));
    }

    const __half* Ab = A + bn * aoffBn;
    auto issue = [&](int stage, int kn) {
        uint32_t sa = sbase + stage * STAGE;
        uint32_t sb = sa + ASTAGE;
        #pragma unroll
        for (int p = 0; p < AP; p++) {
            int gr = bm * MROWS + alr[p];
            cp16(sa + aso[p], Ab + (size_t)gr * Ald + kn + alc[p] * 8,
                 (gr < M) ? 16u : 0u);
        }
        #pragma unroll
        for (int p = 0; p < 4; p++)
            cp16(sb + bso[p], B + (size_t)(bn * 128 + blr[p]) * K + kn + blc[p] * 8, 16u);
        CP_COMMIT();
    };

    issue(0, 0);
    if (K > 64) issue(1, 64);
    else CP_COMMIT();

    const int nchunks = K >> 6;
    for (int ck = 0; ck < nchunks; ck++) {
        CP_WAIT1();
        __syncthreads();
        if (ck + 2 < nchunks) issue((ck + 2) % 3, (ck + 2) * 64);
        else CP_COMMIT();
        uint32_t sAb = sbase + (ck % 3) * STAGE;
        uint32_t sBb = sAb + ASTAGE;
        #pragma unroll
        for (int ks = 0; ks < 4; ks++) {
            const uint32_t c = (uint32_t)(ks * 2 + lch);
            uint32_t af[MT][4];
            #pragma unroll
            for (int mt = 0; mt < MT; mt++)
                LDSM_X4(af[mt][0], af[mt][1], af[mt][2], af[mt][3],
                        sAb + aro[mt] + ((c ^ arx[mt]) << 4));
            uint32_t bf[4][2];
            #pragma unroll
            for (int h = 0; h < 2; h++) {
                uint32_t t0, t1, t2, t3;
                LDSM_X4(t0, t1, t2, t3, sBb + bro[h] + ((c ^ brx[h]) << 4));
                bf[h * 2 + 0][0] = t0; bf[h * 2 + 0][1] = t2;
                bf[h * 2 + 1][0] = t1; bf[h * 2 + 1][1] = t3;
            }
            #pragma unroll
            for (int mt = 0; mt < MT; mt++)
                #pragma unroll
                for (int nt = 0; nt < 4; nt++)
                    mma16816(acc[mt][nt], af[mt], bf[nt]);
        }
    }

    #pragma unroll
    for (int mt = 0; mt < MT; mt++) {
        int gr0 = bm * MROWS + wm + mt * 16 + (lane >> 2);
        #pragma unroll
        for (int nt = 0; nt < 4; nt++) {
            int col = wn + nt * 8 + (lane & 3) * 2;
            int gc = bn * 128 + col;
            if (Ch) {
                float b0 = bias[gc], b1v = bias[gc + 1];
                if (gr0 < M)
                    *(__half2*)(Ch + (size_t)gr0 * NCOLS + gc) =
                        __floats2half2_rn(acc[mt][nt][0] + b0, acc[mt][nt][1] + b1v);
                if (gr0 + 8 < M)
                    *(__half2*)(Ch + (size_t)(gr0 + 8) * NCOLS + gc) =
                        __floats2half2_rn(acc[mt][nt][2] + b0, acc[mt][nt][3] + b1v);
            } else {
                if (gr0 < M)
                    *(float2*)(Cf + (size_t)gr0 * NCOLS + gc) =
                        make_float2(acc[mt][nt][0], acc[mt][nt][1]);
                if (gr0 + 8 < M)
                    *(float2*)(Cf + (size_t)(gr0 + 8) * NCOLS + gc) =
                        make_float2(acc[mt][nt][2], acc[mt][nt][3]);
            }
        }
    }
}

// ---------------- merged prep+proj: weight fp16 transposes + attention projections ----------------
__global__ void prep_proj_k(const float* __restrict__ W1, const float* __restrict__ W2,
                            const float* __restrict__ al1, const float* __restrict__ ar1,
                            const float* __restrict__ al2, const float* __restrict__ ar2,
                            __half* __restrict__ b1, __half* __restrict__ b2,
                            float* __restrict__ wp) {
    int i = blockIdx.x * blockDim.x + threadIdx.x;
    const int PROJ = 1536 * 32;       // proj warps first
    const int S1 = 384 * 128;
    const int S2 = 128 * 384;
    if (i < PROJ) {
        int w = i >> 5, lane = i & 31;
        const float* vec;
        const float* att;
        if (w < 768) {
            int j = (w < 384) ? w : w - 384;
            int h = j >> 7, k = j & 127;
            vec = W1 + k * 384 + h * 128;
            att = ((w < 384) ? al1 : ar1) + h * 128;
        } else {
            int k = (w < 1152) ? (w - 768) : (w - 1152);
            vec = W2 + k * 128;
            att = (w < 1152) ? al2 : ar2;
        }
        float4 a = *(const float4*)(vec + lane * 4);
        float4 b = *(const float4*)(att + lane * 4);
        float s = a.x * b.x + a.y * b.y + a.z * b.z + a.w * b.w;
        #pragma unroll
        for (int o = 16; o; o >>= 1) s += __shfl_xor_sync(0xffffffffu, s, o);
        if (lane == 0) wp[w] = s;
    } else if (i < PROJ + S1) {
        int j = i - PROJ;
        int n = j >> 7, k = j & 127;
        b1[j] = __float2half_rn(W1[k * 384 + n]);
    } else if (i < PROJ + S1 + S2) {
        int j = i - PROJ - S1;
        int n = j / 384, k = j % 384;
        b2[j] = __float2half_rn(W2[k * 128 + n]);
    }
}

// ---------------- score1 + fp16 conversion of x (one warp per node) ----------------
__global__ void score1_k(const float* __restrict__ feats, const float* __restrict__ wp,
                         float* __restrict__ el, float* __restrict__ er,
                         __half* __restrict__ a1) {
    int n = (blockIdx.x * blockDim.x + threadIdx.x) >> 5;
    int lane = threadIdx.x & 31;
    if (n >= NN_NODES) return;
    float4 x = *(const float4*)(feats + (size_t)n * 128 + lane * 4);
    // emit fp16 copy of x
    __half2 p0 = __floats2half2_rn(x.x, x.y);
    __half2 p1 = __floats2half2_rn(x.z, x.w);
    uint2 pack;
    pack.x = *(uint32_t*)&p0;
    pack.y = *(uint32_t*)&p1;
    *(uint2*)(a1 + (size_t)n * 128 + lane * 4) = pack;

    float sl[3], sr[3];
    #pragma unroll
    for (int h = 0; h < 3; h++) {
        float4 a = *(const float4*)(wp + h * 128 + lane * 4);
        float4 b = *(const float4*)(wp + 384 + h * 128 + lane * 4);
        sl[h] = x.x * a.x + x.y * a.y + x.z * a.z + x.w * a.w;
        sr[h] = x.x * b.x + x.y * b.y + x.z * b.z + x.w * b.w;
    }
    #pragma unroll
    for (int h = 0; h < 3; h++)
        #pragma unroll
        for (int o = 16; o; o >>= 1) {
            sl[h] += __shfl_xor_sync(0xffffffffu, sl[h], o);
            sr[h] += __shfl_xor_sync(0xffffffffu, sr[h], o);
        }
    if (lane == 0) {
        #pragma unroll
        for (int h = 0; h < 3; h++) {
            el[n * 4 + h] = sl[h];
            er[n * 4 + h] = sr[h];
        }
    }
}

// ---------------- score2: el2/er2 from rst1 fp16 (one warp per node) ----------------
__global__ void score2_k(const __half* __restrict__ a2, const float* __restrict__ wp,
                         float* __restrict__ el, float* __restrict__ er) {
    int n = (blockIdx.x * blockDim.x + threadIdx.x) >> 5;
    int lane = threadIdx.x & 31;
    if (n >= NN_NODES) return;
    float sl = 0.f, sr = 0.f;
    #pragma unroll
    for (int seg = 0; seg < 3; seg++) {
        int k0 = seg * 128 + lane * 4;
        uint2 raw = *(const uint2*)(a2 + (size_t)n * 384 + k0);
        float2 v0 = __half22float2(*(__half2*)&raw.x);
        float2 v1 = __half22float2(*(__half2*)&raw.y);
        float4 a = *(const float4*)(wp + 768 + k0);
        float4 b = *(const float4*)(wp + 1152 + k0);
        sl += v0.x * a.x + v0.y * a.y + v1.x * a.z + v1.y * a.w;
        sr += v0.x * b.x + v0.y * b.y + v1.x * b.z + v1.y * b.w;
    }
    #pragma unroll
    for (int o = 16; o; o >>= 1) {
        sl += __shfl_xor_sync(0xffffffffu, sl, o);
        sr += __shfl_xor_sync(0xffffffffu, sr, o);
    }
    if (lane == 0) { el[n] = sl; er[n] = sr; }
}

// ---------------- CSR build ----------------
__global__ void count_k(const int* __restrict__ dst, int* row) {
    int e = blockIdx.x * blockDim.x + threadIdx.x;
    if (e < EE_EDGES) atomicAdd(&row[dst[e]], 1);
}
__global__ void scan_block_k(int* __restrict__ row, int* __restrict__ bsums, int n) {
    __shared__ int sm[512];
    int i = blockIdx.x * 512 + threadIdx.x;
    int v = (i < n) ? row[i] : 0;
    sm[threadIdx.x] = v;
    __syncthreads();
    #pragma unroll
    for (int off = 1; off < 512; off <<= 1) {
        int t = (threadIdx.x >= off) ? sm[threadIdx.x - off] : 0;
        __syncthreads();
        sm[threadIdx.x] += t;
        __syncthreads();
    }
    int incl = sm[threadIdx.x];
    if (i < n) row[i] = incl - v;
    if (threadIdx.x == 511) bsums[blockIdx.x] = incl;
}
__global__ void scan_add_k(int* __restrict__ row, const int* __restrict__ bsums,
                           int* __restrict__ cursor, int n, int nb) {
    __shared__ int sb[65];
    int tid = threadIdx.x;
    if (tid == 0) sb[0] = 0;
    if (tid < 64) {
        int v = (tid < nb) ? bsums[tid] : 0;
        int lane = tid & 31;
        #pragma unroll
        for (int o = 1; o < 32; o <<= 1) {
            int t = __shfl_up_sync(0xffffffffu, v, o);
            if (lane >= o) v += t;
        }
        sb[tid + 1] = v;
    }
    __syncthreads();
    if (tid >= 32 && tid < 64) sb[tid + 1] += sb[32];
    __syncthreads();
    int i = blockIdx.x * blockDim.x + tid;
    if (i < n) {
        int v = row[i] + sb[i >> 9];
        row[i] = v;
        cursor[i] = v;
    }
    if (i == 0) row[n] = EE_EDGES;
}
__global__ void scatter_k(const int* __restrict__ src, const int* __restrict__ dst,
                          int* cursor, int* __restrict__ srcp) {
    int e = blockIdx.x * blockDim.x + threadIdx.x;
    if (e < EE_EDGES) {
        int p = atomicAdd(&cursor[dst[e]], 1);
        srcp[p] = src[e];
    }
}

// ---------------- agg1: aggregate 128-dim fp16 x for all 3 heads; warp per dst ----------------
__global__ void agg1_k(const __half* __restrict__ x, const float* __restrict__ el,
                       const float* __restrict__ er, const int* __restrict__ row,
                       const int* __restrict__ srcp, __half* __restrict__ xagg) {
    int d = (blockIdx.x * blockDim.x + threadIdx.x) >> 5;
    int lane = threadIdx.x & 31;
    if (d >= NN_NODES) return;
    int s0 = row[d], s1 = row[d + 1];
    float4 erv = *(const float4*)(er + d * 4);

    float4 acc[3];
    float den[3];
    #pragma unroll
    for (int h = 0; h < 3; h++) {
        acc[h] = make_float4(0.f, 0.f, 0.f, 0.f);
        den[h] = 0.f;
    }
    for (int i = s0; i < s1; ++i) {
        int s = srcp[i];
        float4 elv = *(const float4*)(el + s * 4);
        uint2 raw = *(const uint2*)(x + (size_t)s * 128 + lane * 4);
        float2 v0 = __half22float2(*(__half2*)&raw.x);
        float2 v1 = __half22float2(*(__half2*)&raw.y);
        float e0 = elv.x + erv.x; e0 = (e0 > 0.f) ? e0 : 0.2f * e0;
        float e1 = elv.y + erv.y; e1 = (e1 > 0.f) ? e1 : 0.2f * e1;
        float e2 = elv.z + erv.z; e2 = (e2 > 0.f) ? e2 : 0.2f * e2;
        float w0 = __expf(e0), w1 = __expf(e1), w2 = __expf(e2);
        den[0] += w0; den[1] += w1; den[2] += w2;
        acc[0].x += w0 * v0.x; acc[0].y += w0 * v0.y; acc[0].z += w0 * v1.x; acc[0].w += w0 * v1.y;
        acc[1].x += w1 * v0.x; acc[1].y += w1 * v0.y; acc[1].z += w1 * v1.x; acc[1].w += w1 * v1.y;
        acc[2].x += w2 * v0.x; acc[2].y += w2 * v0.y; acc[2].z += w2 * v1.x; acc[2].w += w2 * v1.y;
    }
    #pragma unroll
    for (int h = 0; h < 3; h++) {
        float inv = 1.0f / den[h];
        __half2 o0 = __floats2half2_rn(acc[h].x * inv, acc[h].y * inv);
        __half2 o1 = __floats2half2_rn(acc[h].z * inv, acc[h].w * inv);
        uint2 pack;
        pack.x = *(uint32_t*)&o0;
        pack.y = *(uint32_t*)&o1;
        *(uint2*)(xagg + (size_t)d * 384 + h * 128 + lane * 4) = pack;
    }
}

// ---------------- agg2: gather fp32 h2 (1 head), +bias; warp per dst ----------------
__global__ void agg2_k(const float* __restrict__ hfeat, const float* __restrict__ el,
                       const float* __restrict__ er, const float* __restrict__ bias,
                       const int* __restrict__ row, const int* __restrict__ srcp,
                       float* __restrict__ out) {
    int d = (blockIdx.x * blockDim.x + threadIdx.x) >> 5;
    int lane = threadIdx.x & 31;
    if (d >= NN_NODES) return;
    int s0 = row[d], s1 = row[d + 1];
    float erd = er[d];

    float4 acc = make_float4(0.f, 0.f, 0.f, 0.f);
    float den = 0.f;
    #pragma unroll 2
    for (int i = s0; i < s1; ++i) {
        int s = srcp[i];
        float e = el[s] + erd;
        e = (e > 0.f) ? e : 0.2f * e;
        float wt = __expf(e);
        den += wt;
        float4 v = *(const float4*)(hfeat + (size_t)s * 128 + lane * 4);
        acc.x += wt * v.x;
        acc.y += wt * v.y;
        acc.z += wt * v.z;
        acc.w += wt * v.w;
    }
    float inv = 1.0f / den;
    float4 b4 = *(const float4*)(bias + lane * 4);
    *(float4*)(out + (size_t)d * 128 + lane * 4) =
        make_float4(acc.x * inv + b4.x, acc.y * inv + b4.y,
                    acc.z * inv + b4.z, acc.w * inv + b4.w);
}

// ---------------- launch ----------------
static inline int cdiv(int a, int b) { return (a + b - 1) / b; }

extern "C" void kernel_launch(void* const* d_in, const int* in_sizes, int n_in,
                              void* d_out, int out_size) {
    const float* feats   = (const float*)d_in[0];
    const float* W1      = (const float*)d_in[1];
    const float* attn_l1 = (const float*)d_in[2];
    const float* attn_r1 = (const float*)d_in[3];
    const float* bias1   = (const float*)d_in[4];
    const float* W2      = (const float*)d_in[5];
    const float* attn_l2 = (const float*)d_in[6];
    const float* attn_r2 = (const float*)d_in[7];
    const float* bias2   = (const float*)d_in[8];
    const int*   src     = (const int*)d_in[9];
    const int*   dst     = (const int*)d_in[10];
    float* out = (float*)d_out;

    float *h2, *el1, *er1, *el2, *er2, *wp;
    int *row, *cursor, *srcp, *bsums;
    __half *a1cat, *xagg, *a2cat, *b1cat, *b2cat;
    cudaGetSymbolAddress((void**)&h2, g_h2);
    cudaGetSymbolAddress((void**)&el1, g_el1);
    cudaGetSymbolAddress((void**)&er1, g_er1);
    cudaGetSymbolAddress((void**)&el2, g_el2);
    cudaGetSymbolAddress((void**)&er2, g_er2);
    cudaGetSymbolAddress((void**)&wp, g_wproj);
    cudaGetSymbolAddress((void**)&row, g_row);
    cudaGetSymbolAddress((void**)&cursor, g_cursor);
    cudaGetSymbolAddress((void**)&srcp, g_srcp);
    cudaGetSymbolAddress((void**)&bsums, g_bsums);
    cudaGetSymbolAddress((void**)&a1cat, g_a1cat);
    cudaGetSymbolAddress((void**)&xagg, g_xagg);
    cudaGetSymbolAddress((void**)&a2cat, g_a2cat);
    cudaGetSymbolAddress((void**)&b1cat, g_b1cat);
    cudaGetSymbolAddress((void**)&b2cat, g_b2cat);

    static cudaStream_t s2 = nullptr;
    static cudaEvent_t evFork = nullptr, evJoin = nullptr, evG1 = nullptr, evS2 = nullptr;
    static bool attrDone = false;
    if (!s2) {
        cudaStreamCreateWithFlags(&s2, cudaStreamNonBlocking);
        cudaEventCreateWithFlags(&evFork, cudaEventDisableTiming);
        cudaEventCreateWithFlags(&evJoin, cudaEventDisableTiming);
        cudaEventCreateWithFlags(&evG1, cudaEventDisableTiming);
        cudaEventCreateWithFlags(&evS2, cudaEventDisableTiming);
    }
    if (!attrDone) {
        cudaFuncSetAttribute(gemm_mma<128>, cudaFuncAttributeMaxDynamicSharedMemorySize,
                             3 * (128 * 128 + 16384));
        cudaFuncSetAttribute(gemm_mma<64>, cudaFuncAttributeMaxDynamicSharedMemorySize,
                             3 * (64 * 128 + 16384));
        attrDone = true;
    }

    const int nb = cdiv(NN_NODES, 512);

    // fork: CSR build on side stream (memset node + 4 kernels)
    cudaEventRecord(evFork, 0);
    cudaStreamWaitEvent(s2, evFork, 0);
    cudaMemsetAsync(row, 0, (NN_NODES + 1) * sizeof(int), s2);
    count_k<<<cdiv(EE_EDGES, 256), 256, 0, s2>>>(dst, row);
    scan_block_k<<<nb, 512, 0, s2>>>(row, bsums, NN_NODES);
    scan_add_k<<<cdiv(NN_NODES, 256), 256, 0, s2>>>(row, bsums, cursor, NN_NODES, nb);
    scatter_k<<<cdiv(EE_EDGES, 256), 256, 0, s2>>>(src, dst, cursor, srcp);
    cudaEventRecord(evJoin, s2);

    // main: merged prep+proj, then score1 (+x fp16 conversion)
    prep_proj_k<<<cdiv(1536 * 32 + 2 * 384 * 128, 256), 256>>>(
        W1, W2, attn_l1, attn_r1, attn_l2, attn_r2, b1cat, b2cat, wp);
    score1_k<<<cdiv(NN_NODES * 32, 256), 256>>>(feats, wp, el1, er1, a1cat);

    // join: aggregate x per head, then per-head GEMM (+bias) -> rst1 fp16
    cudaStreamWaitEvent(0, evJoin, 0);
    agg1_k<<<cdiv(NN_NODES * 32, 256), 256>>>(a1cat, el1, er1, row, srcp, xagg);
    {
        dim3 grid(cdiv(NN_NODES, 128), 3);
        gemm_mma<128><<<grid, 256, 3 * (128 * 128 + 16384)>>>(
            xagg, 384, 128, b1cat, 128, nullptr, a2cat, bias1, NN_NODES, 384);
    }
    cudaEventRecord(evG1, 0);

    // side stream: score2 concurrent with gemm2
    cudaStreamWaitEvent(s2, evG1, 0);
    score2_k<<<cdiv(NN_NODES * 32, 256), 256, 0, s2>>>(a2cat, wp, el2, er2);
    cudaEventRecord(evS2, s2);

    // main: layer-2 GEMM
    {
        dim3 grid(cdiv(NN_NODES, 64), 1);
        gemm_mma<64><<<grid, 256, 3 * (64 * 128 + 16384)>>>(
            a2cat, 384, 0, b2cat, 384, h2, nullptr, nullptr, NN_NODES, 128);
    }
    cudaStreamWaitEvent(0, evS2, 0);
    agg2_k<<<cdiv(NN_NODES * 32, 256), 256>>>(h2, el2, er2, bias2, row, srcp, out);
}